// round 1
// baseline (speedup 1.0000x reference)
#include <cuda_runtime.h>

#define N_NODES 8192
#define D_IN    512
#define D_OUT   256

// ---------------- scratch (device globals: no allocations allowed) ----------
__device__ float g_h[N_NODES * D_OUT];   // 8 MB
__device__ float g_mu[N_NODES];
__device__ float g_xi[N_NODES];

// ---------------- packed f32x2 FMA (B300 FFMA2; 2x scalar FFMA rate) --------
__device__ __forceinline__ unsigned long long f2u(float2 v) {
    union { float2 f; unsigned long long u; } x; x.f = v; return x.u;
}
__device__ __forceinline__ float2 u2f(unsigned long long v) {
    union { float2 f; unsigned long long u; } x; x.u = v; return x.f;
}
__device__ __forceinline__ float2 ffma2(float2 a, float2 b, float2 c) {
    unsigned long long d;
    asm("fma.rn.f32x2 %0, %1, %2, %3;"
        : "=l"(d) : "l"(f2u(a)), "l"(f2u(b)), "l"(f2u(c)));
    return u2f(d);
}

// ============================================================================
// Kernel 1: h = F[8192,512] @ W[512,256]
// Tile 128x64, 256 threads, micro 8x4 (as 8x2 f32x2), K-chunk 16,
// register-prefetch pipeline.
// ============================================================================
#define G1_TM 128
#define G1_TN 64
#define G1_TK 16

__global__ void __launch_bounds__(256) gemm1_kernel(const float* __restrict__ F,
                                                    const float* __restrict__ Wp) {
    __shared__ float As[G1_TK][G1_TM + 4];   // transposed A tile
    __shared__ float Bs[G1_TK][G1_TN];

    const int tid = threadIdx.x;
    const int tx = tid & 15;      // col group: n = tx*4
    const int ty = tid >> 4;      // row group: m = ty*8
    const int mt = blockIdx.x * G1_TM;
    const int nt = blockIdx.y * G1_TN;

    float2 acc[8][2];
#pragma unroll
    for (int r = 0; r < 8; ++r) { acc[r][0] = make_float2(0.f, 0.f); acc[r][1] = make_float2(0.f, 0.f); }

    float4 pA[2], pB;

    // prefetch k-chunk 0
    {
        const int v0 = tid, v1 = tid + 256;
        pA[0] = *(const float4*)&F[(size_t)(mt + (v0 >> 2)) * D_IN + ((v0 & 3) * 4)];
        pA[1] = *(const float4*)&F[(size_t)(mt + (v1 >> 2)) * D_IN + ((v1 & 3) * 4)];
        pB    = *(const float4*)&Wp[(size_t)(tid >> 4) * D_OUT + nt + (tid & 15) * 4];
    }

    const int NK = D_IN / G1_TK;   // 32
    for (int kt = 0; kt < NK; ++kt) {
        __syncthreads();
        // store phase
#pragma unroll
        for (int k2 = 0; k2 < 2; ++k2) {
            const int v = tid + 256 * k2;
            const int row = v >> 2, q = v & 3;
            As[q * 4 + 0][row] = pA[k2].x;
            As[q * 4 + 1][row] = pA[k2].y;
            As[q * 4 + 2][row] = pA[k2].z;
            As[q * 4 + 3][row] = pA[k2].w;
        }
        {
            const int k = tid >> 4, nq = tid & 15;
            *(float4*)&Bs[k][nq * 4] = pB;
        }
        // prefetch next chunk
        if (kt + 1 < NK) {
            const int k0 = (kt + 1) * G1_TK;
            const int v0 = tid, v1 = tid + 256;
            pA[0] = *(const float4*)&F[(size_t)(mt + (v0 >> 2)) * D_IN + k0 + ((v0 & 3) * 4)];
            pA[1] = *(const float4*)&F[(size_t)(mt + (v1 >> 2)) * D_IN + k0 + ((v1 & 3) * 4)];
            pB    = *(const float4*)&Wp[(size_t)(k0 + (tid >> 4)) * D_OUT + nt + (tid & 15) * 4];
        }
        __syncthreads();
        // compute
#pragma unroll
        for (int k = 0; k < G1_TK; ++k) {
            const float4 a0 = *(const float4*)&As[k][ty * 8];
            const float4 a1 = *(const float4*)&As[k][ty * 8 + 4];
            const float4 b  = *(const float4*)&Bs[k][tx * 4];
            const float2 b0 = make_float2(b.x, b.y);
            const float2 b1 = make_float2(b.z, b.w);
            const float ar[8] = {a0.x, a0.y, a0.z, a0.w, a1.x, a1.y, a1.z, a1.w};
#pragma unroll
            for (int r = 0; r < 8; ++r) {
                const float2 ab = make_float2(ar[r], ar[r]);
                acc[r][0] = ffma2(b0, ab, acc[r][0]);
                acc[r][1] = ffma2(b1, ab, acc[r][1]);
            }
        }
    }
    // epilogue
#pragma unroll
    for (int r = 0; r < 8; ++r) {
        const int row = mt + ty * 8 + r;
        float4 o;
        o.x = acc[r][0].x; o.y = acc[r][0].y; o.z = acc[r][1].x; o.w = acc[r][1].y;
        *(float4*)&g_h[(size_t)row * D_OUT + nt + tx * 4] = o;
    }
}

// ============================================================================
// Kernel 2: mu = h @ w_mu, xi = h @ w_xi  (one warp per row)
// ============================================================================
__global__ void __launch_bounds__(256) muxi_kernel(const float* __restrict__ wmu,
                                                   const float* __restrict__ wxi) {
    __shared__ float smu[D_OUT], sxi[D_OUT];
    const int tid = threadIdx.x;
    smu[tid] = wmu[tid];
    sxi[tid] = wxi[tid];
    __syncthreads();
    const int warp = tid >> 5, lane = tid & 31;
    const int row = blockIdx.x * 8 + warp;
    const float* hr = &g_h[(size_t)row * D_OUT];
    float sm = 0.f, sx = 0.f;
#pragma unroll
    for (int i = 0; i < D_OUT / 32; ++i) {
        const float hv = hr[lane + 32 * i];
        sm += hv * smu[lane + 32 * i];
        sx += hv * sxi[lane + 32 * i];
    }
#pragma unroll
    for (int o = 16; o; o >>= 1) {
        sm += __shfl_xor_sync(0xFFFFFFFFu, sm, o);
        sx += __shfl_xor_sync(0xFFFFFFFFu, sx, o);
    }
    if (lane == 0) { g_mu[row] = sm; g_xi[row] = sx; }
}

// ============================================================================
// Kernel 3: fused masked-softmax aggregation + ELU
//   w_ij = adj ? exp(lrelu(mu_i + xi_j)) : 0   (no max-subtraction needed:
//   mu,xi are O(0.5) so exp stays in [0.1, ~12])
//   out_i = elu( (sum_j w_ij h_j) / (sum_j w_ij) )
// TM=64 rows/CTA (grid 128), TJ=32 j-tile, 256 threads,
// per-thread micro 4 rows x 16 cols (f32x2), register-prefetch pipeline.
// ============================================================================
#define TM 64
#define TJ 32
#define WPAD 68   // 16B-aligned padded row stride for transposed w tile

__global__ void __launch_bounds__(256) attn_kernel(const int* __restrict__ adj,
                                                   float* __restrict__ out) {
    __shared__ float sh_h[TJ][D_OUT];      // 32 KB
    __shared__ float sh_w[TJ][WPAD];       // w transposed [j][row], 8.5 KB
    __shared__ float sh_mu[TM];
    __shared__ float sh_rs[TM];

    const int tid = threadIdx.x;
    const int tx = tid & 15;       // col group
    const int ty = tid >> 4;       // row group: rows r0..r0+3, r0 = ty*4
    const int r0 = ty * 4;
    const int tx4 = tx * 4;
    const int row0 = blockIdx.x * TM;

    if (tid < TM) sh_mu[tid] = g_mu[row0 + tid];

    float2 acc[4][8];
#pragma unroll
    for (int r = 0; r < 4; ++r)
#pragma unroll
        for (int c = 0; c < 8; ++c) acc[r][c] = make_float2(0.f, 0.f);
    float ds[4] = {0.f, 0.f, 0.f, 0.f};   // row-sum partials (valid on tx==0)

    int4   pa[2];   // adjacency prefetch: 2 int4 per thread (64 rows x 32 j)
    float4 ph[8];   // h prefetch: 8 float4 per thread (32 j x 256 cols)

    // prefetch tile 0
#pragma unroll
    for (int k = 0; k < 2; ++k) {
        const int v = tid + 256 * k;
        pa[k] = __ldg(reinterpret_cast<const int4*>(adj + (size_t)(row0 + (v >> 3)) * N_NODES) + (v & 7));
    }
#pragma unroll
    for (int k = 0; k < 8; ++k) {
        const int v = tid + 256 * k;
        ph[k] = __ldg(reinterpret_cast<const float4*>(g_h + (size_t)(v >> 6) * D_OUT) + (v & 63));
    }

    const int NT = N_NODES / TJ;   // 256
    for (int t = 0; t < NT; ++t) {
        const int j0 = t * TJ;
        __syncthreads();
        // ---- store phase: h tile + compute w tile ----
#pragma unroll
        for (int k = 0; k < 8; ++k) {
            const int v = tid + 256 * k;
            *(float4*)&sh_h[v >> 6][(v & 63) * 4] = ph[k];
        }
#pragma unroll
        for (int k = 0; k < 2; ++k) {
            const int v = tid + 256 * k;
            const int row = v >> 3, jq = v & 7;
            const float mur = sh_mu[row];
            const int av[4] = {pa[k].x, pa[k].y, pa[k].z, pa[k].w};
#pragma unroll
            for (int s = 0; s < 4; ++s) {
                const int j = jq * 4 + s;
                float tt = mur + __ldg(&g_xi[j0 + j]);
                tt = fmaxf(tt, 0.2f * tt);                    // LeakyReLU
                const float w = (av[s] > 0) ? __expf(tt) : 0.0f;
                sh_w[j][row] = w;
            }
        }
        // ---- prefetch next tile (latency hidden under compute) ----
        if (t + 1 < NT) {
            const int j1 = j0 + TJ;
#pragma unroll
            for (int k = 0; k < 2; ++k) {
                const int v = tid + 256 * k;
                pa[k] = __ldg(reinterpret_cast<const int4*>(adj + (size_t)(row0 + (v >> 3)) * N_NODES + j1) + (v & 7));
            }
#pragma unroll
            for (int k = 0; k < 8; ++k) {
                const int v = tid + 256 * k;
                ph[k] = __ldg(reinterpret_cast<const float4*>(g_h + (size_t)(j1 + (v >> 6)) * D_OUT) + (v & 63));
            }
        }
        __syncthreads();
        // ---- compute phase ----
#pragma unroll 4
        for (int j = 0; j < TJ; ++j) {
            const float4 w4 = *(const float4*)&sh_w[j][r0];
            if (tx == 0) { ds[0] += w4.x; ds[1] += w4.y; ds[2] += w4.z; ds[3] += w4.w; }
            const float2 wb[4] = {make_float2(w4.x, w4.x), make_float2(w4.y, w4.y),
                                  make_float2(w4.z, w4.z), make_float2(w4.w, w4.w)};
#pragma unroll
            for (int q = 0; q < 4; ++q) {
                const float4 hv = *(const float4*)&sh_h[j][q * 64 + tx4];
                const float2 h0 = make_float2(hv.x, hv.y);
                const float2 h1 = make_float2(hv.z, hv.w);
#pragma unroll
                for (int r = 0; r < 4; ++r) {
                    acc[r][2 * q]     = ffma2(h0, wb[r], acc[r][2 * q]);
                    acc[r][2 * q + 1] = ffma2(h1, wb[r], acc[r][2 * q + 1]);
                }
            }
        }
    }

    // ---- epilogue: divide by row sum, ELU, store ----
    __syncthreads();
    if (tx == 0) {
        sh_rs[r0 + 0] = ds[0]; sh_rs[r0 + 1] = ds[1];
        sh_rs[r0 + 2] = ds[2]; sh_rs[r0 + 3] = ds[3];
    }
    __syncthreads();
#pragma unroll
    for (int r = 0; r < 4; ++r) {
        const float inv = 1.0f / sh_rs[r0 + r];
        const size_t ro = (size_t)(row0 + r0 + r) * D_OUT;
#pragma unroll
        for (int q = 0; q < 4; ++q) {
            float v0 = acc[r][2 * q].x * inv;
            float v1 = acc[r][2 * q].y * inv;
            float v2 = acc[r][2 * q + 1].x * inv;
            float v3 = acc[r][2 * q + 1].y * inv;
            float4 o;
            o.x = (v0 > 0.f) ? v0 : expm1f(v0);
            o.y = (v1 > 0.f) ? v1 : expm1f(v1);
            o.z = (v2 > 0.f) ? v2 : expm1f(v2);
            o.w = (v3 > 0.f) ? v3 : expm1f(v3);
            *(float4*)&out[ro + q * 64 + tx4] = o;
        }
    }
}

// ============================================================================
extern "C" void kernel_launch(void* const* d_in, const int* in_sizes, int n_in,
                              void* d_out, int out_size) {
    const float* F   = (const float*)d_in[0];
    const int*   adj = (const int*)d_in[1];
    const float* Wp  = (const float*)d_in[2];
    const float* wmu = (const float*)d_in[3];
    const float* wxi = (const float*)d_in[4];
    float* out = (float*)d_out;

    dim3 g1(N_NODES / G1_TM, D_OUT / G1_TN);   // 64 x 4
    gemm1_kernel<<<g1, 256>>>(F, Wp);
    muxi_kernel<<<N_NODES / 8, 256>>>(wmu, wxi);
    attn_kernel<<<N_NODES / TM, 256>>>(adj, out);
}

// round 2
// speedup vs baseline: 1.0670x; 1.0670x over previous
#include <cuda_runtime.h>

#define N_NODES 8192
#define D_IN    512
#define D_OUT   256

// ---------------- scratch (device globals: no allocations allowed) ----------
__device__ float g_h[N_NODES * D_OUT];   // 8 MB
__device__ float g_mu[N_NODES];
__device__ float g_xi[N_NODES];

// ---------------- packed f32x2 FMA (B300 FFMA2; 2x scalar FFMA rate) --------
__device__ __forceinline__ unsigned long long f2u(float2 v) {
    union { float2 f; unsigned long long u; } x; x.f = v; return x.u;
}
__device__ __forceinline__ float2 u2f(unsigned long long v) {
    union { float2 f; unsigned long long u; } x; x.u = v; return x.f;
}
__device__ __forceinline__ float2 ffma2(float2 a, float2 b, float2 c) {
    unsigned long long d;
    asm("fma.rn.f32x2 %0, %1, %2, %3;"
        : "=l"(d) : "l"(f2u(a)), "l"(f2u(b)), "l"(f2u(c)));
    return u2f(d);
}

// ============================================================================
// Kernel 1: h = F[8192,512] @ W[512,256]
// Tile 128x64, 256 threads, micro 8x4 (as 8x2 f32x2), K-chunk 16,
// register-prefetch pipeline.
// ============================================================================
#define G1_TM 128
#define G1_TN 64
#define G1_TK 16

__global__ void __launch_bounds__(256) gemm1_kernel(const float* __restrict__ F,
                                                    const float* __restrict__ Wp) {
    __shared__ float As[G1_TK][G1_TM + 4];   // transposed A tile
    __shared__ float Bs[G1_TK][G1_TN];

    const int tid = threadIdx.x;
    const int tx = tid & 15;      // col group: n = tx*4
    const int ty = tid >> 4;      // row group: m = ty*8
    const int mt = blockIdx.x * G1_TM;
    const int nt = blockIdx.y * G1_TN;

    float2 acc[8][2];
#pragma unroll
    for (int r = 0; r < 8; ++r) { acc[r][0] = make_float2(0.f, 0.f); acc[r][1] = make_float2(0.f, 0.f); }

    float4 pA[2], pB;

    // prefetch k-chunk 0
    {
        const int v0 = tid, v1 = tid + 256;
        pA[0] = *(const float4*)&F[(size_t)(mt + (v0 >> 2)) * D_IN + ((v0 & 3) * 4)];
        pA[1] = *(const float4*)&F[(size_t)(mt + (v1 >> 2)) * D_IN + ((v1 & 3) * 4)];
        pB    = *(const float4*)&Wp[(size_t)(tid >> 4) * D_OUT + nt + (tid & 15) * 4];
    }

    const int NK = D_IN / G1_TK;   // 32
    for (int kt = 0; kt < NK; ++kt) {
        __syncthreads();
        // store phase
#pragma unroll
        for (int k2 = 0; k2 < 2; ++k2) {
            const int v = tid + 256 * k2;
            const int row = v >> 2, q = v & 3;
            As[q * 4 + 0][row] = pA[k2].x;
            As[q * 4 + 1][row] = pA[k2].y;
            As[q * 4 + 2][row] = pA[k2].z;
            As[q * 4 + 3][row] = pA[k2].w;
        }
        {
            const int k = tid >> 4, nq = tid & 15;
            *(float4*)&Bs[k][nq * 4] = pB;
        }
        // prefetch next chunk
        if (kt + 1 < NK) {
            const int k0 = (kt + 1) * G1_TK;
            const int v0 = tid, v1 = tid + 256;
            pA[0] = *(const float4*)&F[(size_t)(mt + (v0 >> 2)) * D_IN + k0 + ((v0 & 3) * 4)];
            pA[1] = *(const float4*)&F[(size_t)(mt + (v1 >> 2)) * D_IN + k0 + ((v1 & 3) * 4)];
            pB    = *(const float4*)&Wp[(size_t)(k0 + (tid >> 4)) * D_OUT + nt + (tid & 15) * 4];
        }
        __syncthreads();
        // compute
#pragma unroll
        for (int k = 0; k < G1_TK; ++k) {
            const float4 a0 = *(const float4*)&As[k][ty * 8];
            const float4 a1 = *(const float4*)&As[k][ty * 8 + 4];
            const float4 b  = *(const float4*)&Bs[k][tx * 4];
            const float2 b0 = make_float2(b.x, b.y);
            const float2 b1 = make_float2(b.z, b.w);
            const float ar[8] = {a0.x, a0.y, a0.z, a0.w, a1.x, a1.y, a1.z, a1.w};
#pragma unroll
            for (int r = 0; r < 8; ++r) {
                const float2 ab = make_float2(ar[r], ar[r]);
                acc[r][0] = ffma2(b0, ab, acc[r][0]);
                acc[r][1] = ffma2(b1, ab, acc[r][1]);
            }
        }
    }
    // epilogue
#pragma unroll
    for (int r = 0; r < 8; ++r) {
        const int row = mt + ty * 8 + r;
        float4 o;
        o.x = acc[r][0].x; o.y = acc[r][0].y; o.z = acc[r][1].x; o.w = acc[r][1].y;
        *(float4*)&g_h[(size_t)row * D_OUT + nt + tx * 4] = o;
    }
}

// ============================================================================
// Kernel 2: mu = h @ w_mu, xi = h @ w_xi  (one warp per row)
// ============================================================================
__global__ void __launch_bounds__(256) muxi_kernel(const float* __restrict__ wmu,
                                                   const float* __restrict__ wxi) {
    __shared__ float smu[D_OUT], sxi[D_OUT];
    const int tid = threadIdx.x;
    smu[tid] = wmu[tid];
    sxi[tid] = wxi[tid];
    __syncthreads();
    const int warp = tid >> 5, lane = tid & 31;
    const int row = blockIdx.x * 8 + warp;
    const float* hr = &g_h[(size_t)row * D_OUT];
    float sm = 0.f, sx = 0.f;
#pragma unroll
    for (int i = 0; i < D_OUT / 32; ++i) {
        const float hv = hr[lane + 32 * i];
        sm += hv * smu[lane + 32 * i];
        sx += hv * sxi[lane + 32 * i];
    }
#pragma unroll
    for (int o = 16; o; o >>= 1) {
        sm += __shfl_xor_sync(0xFFFFFFFFu, sm, o);
        sx += __shfl_xor_sync(0xFFFFFFFFu, sx, o);
    }
    if (lane == 0) { g_mu[row] = sm; g_xi[row] = sx; }
}

// ============================================================================
// Kernel 3: fused masked-softmax aggregation + ELU
//   w_ij = adj ? exp(lrelu(mu_i + xi_j)) : 0   (no max-subtraction needed:
//   mu,xi are O(0.5) so exp stays in [0.1, ~12])
//   out_i = elu( (sum_j w_ij h_j) / (sum_j w_ij) )
// TM=64 rows/CTA (grid 128), TJ=32 j-tile, 256 threads,
// per-thread micro 4 rows x 16 cols (f32x2), register-prefetch pipeline.
// ============================================================================
#define TM 64
#define TJ 32
#define WPAD 68   // 16B-aligned padded row stride for transposed w tile

__global__ void __launch_bounds__(256) attn_kernel(const int* __restrict__ adj,
                                                   float* __restrict__ out) {
    __shared__ float sh_h[TJ][D_OUT];      // 32 KB
    __shared__ float sh_w[TJ][WPAD];       // w transposed [j][row], 8.5 KB
    __shared__ float sh_mu[TM];
    __shared__ float sh_rs[TM];

    const int tid = threadIdx.x;
    const int tx = tid & 15;       // col group
    const int ty = tid >> 4;       // row group: rows r0..r0+3, r0 = ty*4
    const int r0 = ty * 4;
    const int tx4 = tx * 4;
    const int row0 = blockIdx.x * TM;

    if (tid < TM) sh_mu[tid] = g_mu[row0 + tid];

    float2 acc[4][8];
#pragma unroll
    for (int r = 0; r < 4; ++r)
#pragma unroll
        for (int c = 0; c < 8; ++c) acc[r][c] = make_float2(0.f, 0.f);
    float ds[4] = {0.f, 0.f, 0.f, 0.f};   // row-sum partials (valid on tx==0)

    int4   pa[2];   // adjacency prefetch: 2 int4 per thread (64 rows x 32 j)
    float4 ph[8];   // h prefetch: 8 float4 per thread (32 j x 256 cols)

    // prefetch tile 0
#pragma unroll
    for (int k = 0; k < 2; ++k) {
        const int v = tid + 256 * k;
        pa[k] = __ldg(reinterpret_cast<const int4*>(adj + (size_t)(row0 + (v >> 3)) * N_NODES) + (v & 7));
    }
#pragma unroll
    for (int k = 0; k < 8; ++k) {
        const int v = tid + 256 * k;
        ph[k] = __ldg(reinterpret_cast<const float4*>(g_h + (size_t)(v >> 6) * D_OUT) + (v & 63));
    }

    const int NT = N_NODES / TJ;   // 256
    for (int t = 0; t < NT; ++t) {
        const int j0 = t * TJ;
        __syncthreads();
        // ---- store phase: h tile + compute w tile ----
#pragma unroll
        for (int k = 0; k < 8; ++k) {
            const int v = tid + 256 * k;
            *(float4*)&sh_h[v >> 6][(v & 63) * 4] = ph[k];
        }
#pragma unroll
        for (int k = 0; k < 2; ++k) {
            const int v = tid + 256 * k;
            const int row = v >> 3, jq = v & 7;
            const float mur = sh_mu[row];
            const int av[4] = {pa[k].x, pa[k].y, pa[k].z, pa[k].w};
#pragma unroll
            for (int s = 0; s < 4; ++s) {
                const int j = jq * 4 + s;
                float tt = mur + __ldg(&g_xi[j0 + j]);
                tt = fmaxf(tt, 0.2f * tt);                    // LeakyReLU
                const float w = (av[s] > 0) ? __expf(tt) : 0.0f;
                sh_w[j][row] = w;
            }
        }
        // ---- prefetch next tile (latency hidden under compute) ----
        if (t + 1 < NT) {
            const int j1 = j0 + TJ;
#pragma unroll
            for (int k = 0; k < 2; ++k) {
                const int v = tid + 256 * k;
                pa[k] = __ldg(reinterpret_cast<const int4*>(adj + (size_t)(row0 + (v >> 3)) * N_NODES + j1) + (v & 7));
            }
#pragma unroll
            for (int k = 0; k < 8; ++k) {
                const int v = tid + 256 * k;
                ph[k] = __ldg(reinterpret_cast<const float4*>(g_h + (size_t)(j1 + (v >> 6)) * D_OUT) + (v & 63));
            }
        }
        __syncthreads();
        // ---- compute phase ----
#pragma unroll 4
        for (int j = 0; j < TJ; ++j) {
            const float4 w4 = *(const float4*)&sh_w[j][r0];
            if (tx == 0) { ds[0] += w4.x; ds[1] += w4.y; ds[2] += w4.z; ds[3] += w4.w; }
            const float2 wb[4] = {make_float2(w4.x, w4.x), make_float2(w4.y, w4.y),
                                  make_float2(w4.z, w4.z), make_float2(w4.w, w4.w)};
#pragma unroll
            for (int q = 0; q < 4; ++q) {
                const float4 hv = *(const float4*)&sh_h[j][q * 64 + tx4];
                const float2 h0 = make_float2(hv.x, hv.y);
                const float2 h1 = make_float2(hv.z, hv.w);
#pragma unroll
                for (int r = 0; r < 4; ++r) {
                    acc[r][2 * q]     = ffma2(h0, wb[r], acc[r][2 * q]);
                    acc[r][2 * q + 1] = ffma2(h1, wb[r], acc[r][2 * q + 1]);
                }
            }
        }
    }

    // ---- epilogue: divide by row sum, ELU, store ----
    __syncthreads();
    if (tx == 0) {
        sh_rs[r0 + 0] = ds[0]; sh_rs[r0 + 1] = ds[1];
        sh_rs[r0 + 2] = ds[2]; sh_rs[r0 + 3] = ds[3];
    }
    __syncthreads();
#pragma unroll
    for (int r = 0; r < 4; ++r) {
        const float inv = 1.0f / sh_rs[r0 + r];
        const size_t ro = (size_t)(row0 + r0 + r) * D_OUT;
#pragma unroll
        for (int q = 0; q < 4; ++q) {
            float v0 = acc[r][2 * q].x * inv;
            float v1 = acc[r][2 * q].y * inv;
            float v2 = acc[r][2 * q + 1].x * inv;
            float v3 = acc[r][2 * q + 1].y * inv;
            float4 o;
            o.x = (v0 > 0.f) ? v0 : expm1f(v0);
            o.y = (v1 > 0.f) ? v1 : expm1f(v1);
            o.z = (v2 > 0.f) ? v2 : expm1f(v2);
            o.w = (v3 > 0.f) ? v3 : expm1f(v3);
            *(float4*)&out[ro + q * 64 + tx4] = o;
        }
    }
}

// ============================================================================
extern "C" void kernel_launch(void* const* d_in, const int* in_sizes, int n_in,
                              void* d_out, int out_size) {
    const float* F   = (const float*)d_in[0];
    const int*   adj = (const int*)d_in[1];
    const float* Wp  = (const float*)d_in[2];
    const float* wmu = (const float*)d_in[3];
    const float* wxi = (const float*)d_in[4];
    float* out = (float*)d_out;

    dim3 g1(N_NODES / G1_TM, D_OUT / G1_TN);   // 64 x 4
    gemm1_kernel<<<g1, 256>>>(F, Wp);
    muxi_kernel<<<N_NODES / 8, 256>>>(wmu, wxi);
    attn_kernel<<<N_NODES / TM, 256>>>(adj, out);
}

// round 6
// speedup vs baseline: 1.8212x; 1.7069x over previous
#include <cuda_runtime.h>
#include <cstdint>

#define N_NODES 8192
#define D_IN    512
#define D_OUT   256
#define KTILE   32
#define NT      (N_NODES / KTILE)   // 256
#define TM      64

__device__ float g_h [(size_t)N_NODES * D_OUT];
__device__ float g_hT[(size_t)D_OUT * N_NODES];   // tf32-rounded, [col][node]
__device__ float g_mu[N_NODES];
__device__ float g_xi[N_NODES];

__device__ __forceinline__ unsigned long long f2u(float2 v) { union { float2 f; unsigned long long u; } x; x.f = v; return x.u; }
__device__ __forceinline__ float2 u2f(unsigned long long v) { union { float2 f; unsigned long long u; } x; x.u = v; return x.f; }
__device__ __forceinline__ float2 ffma2(float2 a, float2 b, float2 c) {
    unsigned long long d;
    asm("fma.rn.f32x2 %0, %1, %2, %3;" : "=l"(d) : "l"(f2u(a)), "l"(f2u(b)), "l"(f2u(c)));
    return u2f(d);
}

// ======================= gemm1: h = F @ W (fp32 SIMT, known-good) ===========
#define G1_TM 128
#define G1_TN 64
#define G1_TK 16
__global__ void __launch_bounds__(256) gemm1_kernel(const float* __restrict__ F,
                                                    const float* __restrict__ Wp) {
    __shared__ float As[G1_TK][G1_TM + 4];
    __shared__ float Bs[G1_TK][G1_TN];
    const int tid = threadIdx.x, tx = tid & 15, ty = tid >> 4;
    const int mt = blockIdx.x * G1_TM, nt = blockIdx.y * G1_TN;
    float2 acc[8][2];
#pragma unroll
    for (int r = 0; r < 8; ++r) { acc[r][0] = make_float2(0.f, 0.f); acc[r][1] = make_float2(0.f, 0.f); }
    float4 pA[2], pB;
    {
        const int v0 = tid, v1 = tid + 256;
        pA[0] = *(const float4*)&F[(size_t)(mt + (v0 >> 2)) * D_IN + ((v0 & 3) * 4)];
        pA[1] = *(const float4*)&F[(size_t)(mt + (v1 >> 2)) * D_IN + ((v1 & 3) * 4)];
        pB    = *(const float4*)&Wp[(size_t)(tid >> 4) * D_OUT + nt + (tid & 15) * 4];
    }
    const int NK = D_IN / G1_TK;
    for (int kt = 0; kt < NK; ++kt) {
        __syncthreads();
#pragma unroll
        for (int k2 = 0; k2 < 2; ++k2) {
            const int v = tid + 256 * k2, row = v >> 2, q = v & 3;
            As[q * 4 + 0][row] = pA[k2].x; As[q * 4 + 1][row] = pA[k2].y;
            As[q * 4 + 2][row] = pA[k2].z; As[q * 4 + 3][row] = pA[k2].w;
        }
        *(float4*)&Bs[tid >> 4][(tid & 15) * 4] = pB;
        if (kt + 1 < NK) {
            const int k0 = (kt + 1) * G1_TK, v0 = tid, v1 = tid + 256;
            pA[0] = *(const float4*)&F[(size_t)(mt + (v0 >> 2)) * D_IN + k0 + ((v0 & 3) * 4)];
            pA[1] = *(const float4*)&F[(size_t)(mt + (v1 >> 2)) * D_IN + k0 + ((v1 & 3) * 4)];
            pB    = *(const float4*)&Wp[(size_t)(k0 + (tid >> 4)) * D_OUT + nt + (tid & 15) * 4];
        }
        __syncthreads();
#pragma unroll
        for (int k = 0; k < G1_TK; ++k) {
            const float4 a0 = *(const float4*)&As[k][ty * 8];
            const float4 a1 = *(const float4*)&As[k][ty * 8 + 4];
            const float4 b  = *(const float4*)&Bs[k][tx * 4];
            const float2 b0 = make_float2(b.x, b.y), b1 = make_float2(b.z, b.w);
            const float ar[8] = {a0.x, a0.y, a0.z, a0.w, a1.x, a1.y, a1.z, a1.w};
#pragma unroll
            for (int r = 0; r < 8; ++r) {
                const float2 ab = make_float2(ar[r], ar[r]);
                acc[r][0] = ffma2(b0, ab, acc[r][0]);
                acc[r][1] = ffma2(b1, ab, acc[r][1]);
            }
        }
    }
#pragma unroll
    for (int r = 0; r < 8; ++r) {
        float4 o; o.x = acc[r][0].x; o.y = acc[r][0].y; o.z = acc[r][1].x; o.w = acc[r][1].y;
        *(float4*)&g_h[(size_t)(mt + ty * 8 + r) * D_OUT + nt + tx * 4] = o;
    }
}

// ======================= muxi ==============================================
__global__ void __launch_bounds__(256) muxi_kernel(const float* __restrict__ wmu,
                                                   const float* __restrict__ wxi) {
    __shared__ float smu[D_OUT], sxi[D_OUT];
    const int tid = threadIdx.x;
    smu[tid] = wmu[tid]; sxi[tid] = wxi[tid];
    __syncthreads();
    const int warp = tid >> 5, lane = tid & 31;
    const int row = blockIdx.x * 8 + warp;
    const float* hr = &g_h[(size_t)row * D_OUT];
    float sm = 0.f, sx = 0.f;
#pragma unroll
    for (int i = 0; i < D_OUT / 32; ++i) {
        const float hv = hr[lane + 32 * i];
        sm += hv * smu[lane + 32 * i];
        sx += hv * sxi[lane + 32 * i];
    }
#pragma unroll
    for (int o = 16; o; o >>= 1) {
        sm += __shfl_xor_sync(0xFFFFFFFFu, sm, o);
        sx += __shfl_xor_sync(0xFFFFFFFFu, sx, o);
    }
    if (lane == 0) { g_mu[row] = sm; g_xi[row] = sx; }
}

// ======================= transpose h -> hT (tf32-rounded) ===================
__global__ void __launch_bounds__(256) transpose_kernel() {
    __shared__ float tile[32][33];
    const int x = threadIdx.x & 31, y = threadIdx.x >> 5;
    const int bi = blockIdx.x * 32, bc = blockIdx.y * 32;
#pragma unroll
    for (int k = 0; k < 32; k += 8) {
        float v = g_h[(size_t)(bi + y + k) * D_OUT + bc + x];
        uint32_t u; asm("cvt.rna.tf32.f32 %0, %1;" : "=r"(u) : "f"(v));
        tile[y + k][x] = __uint_as_float(u);
    }
    __syncthreads();
#pragma unroll
    for (int k = 0; k < 32; k += 8)
        g_hT[(size_t)(bc + y + k) * N_NODES + bi + x] = tile[x][y + k];
}

// ======================= attn: mma.sync tf32 flash-GAT ======================
// SMEM (floats):  mus[64] | rs[64] | W 2 x (64 x 36) | B 3 x (256 x 36)
#define WSTR 36
#define OFF_MU_F 0
#define OFF_RS_F 64
#define OFF_W_F  128
#define WSTAGE_F (TM * WSTR)                 // 2304
#define OFF_B_F  (OFF_W_F + 2 * WSTAGE_F)    // 4736
#define BSTAGE_F (D_OUT * WSTR)              // 9216
#define ATTN_SMEM ((OFF_B_F + 3 * BSTAGE_F) * 4)   // 129536 bytes

__device__ __forceinline__ void mma_tf32(float* d, const uint32_t* a, uint32_t b0, uint32_t b1) {
    asm volatile("mma.sync.aligned.m16n8k8.row.col.f32.tf32.tf32.f32 "
        "{%0,%1,%2,%3}, {%4,%5,%6,%7}, {%8,%9}, {%0,%1,%2,%3};"
        : "+f"(d[0]), "+f"(d[1]), "+f"(d[2]), "+f"(d[3])
        : "r"(a[0]), "r"(a[1]), "r"(a[2]), "r"(a[3]), "r"(b0), "r"(b1));
}

__global__ void __launch_bounds__(256, 1) attn_kernel(const int* __restrict__ adj,
                                                      float* __restrict__ out) {
    extern __shared__ float sm[];
    float* mus = sm + OFF_MU_F;
    float* rs  = sm + OFF_RS_F;
    float* Ws  = sm + OFF_W_F;
    float* Bss = sm + OFF_B_F;

    const int tid = threadIdx.x;
    const int lane = tid & 31;
    const int g = lane >> 2, tq = lane & 3;
    const int warp = tid >> 5;
    const int m0 = (warp >> 2) * 32;       // warp row base (0 or 32)
    const int n0 = (warp & 3) * 64;        // warp col base
    const int row0 = blockIdx.x * TM;

    // W-gen role: thread (wrow, wq) handles row wrow, j-chunk wq*8..wq*8+7
    const int wrow = tid >> 2;             // 0..63
    const int wq = tid & 3;
    const int j8 = wq * 8;

    if (tid < TM) mus[tid] = g_mu[row0 + tid];
    __syncthreads();
    const float mur = mus[wrow];

    const int4* adjb = (const int4*)(adj + (size_t)(row0 + wrow) * N_NODES) + wq * 2;

    float acc[2][8][4];
#pragma unroll
    for (int mt = 0; mt < 2; ++mt)
#pragma unroll
        for (int nt = 0; nt < 8; ++nt)
#pragma unroll
            for (int c = 0; c < 4; ++c) acc[mt][nt][c] = 0.f;
    float dsum = 0.f;

#define CPB(t) do { \
        float* dst0 = Bss + ((t) % 3) * BSTAGE_F; \
        _Pragma("unroll") \
        for (int i = 0; i < 8; ++i) { \
            const int c = tid + 256 * i; \
            const int n = c >> 3, k16 = c & 7; \
            uint32_t d; \
            asm("{ .reg .u64 tt; cvta.to.shared.u64 tt, %1; cvt.u32.u64 %0, tt; }" \
                : "=r"(d) : "l"(dst0 + n * WSTR + k16 * 4)); \
            const float* s = g_hT + (size_t)n * N_NODES + (t) * KTILE + k16 * 4; \
            asm volatile("cp.async.cg.shared.global [%0], [%1], 16;" :: "r"(d), "l"(s)); \
        } } while (0)

#define LDPRE(t, ai, xi0, xi1) do { \
        (ai)[0] = __ldg(adjb + (t) * 8); \
        (ai)[1] = __ldg(adjb + (t) * 8 + 1); \
        const float4* xb = (const float4*)(g_xi + (t) * KTILE + j8); \
        (xi0) = __ldg(xb); (xi1) = __ldg(xb + 1); \
    } while (0)

#define GENW(t, ai, xi0, xi1) do { \
        uint32_t wt[8]; \
        const int am[8] = {(ai)[0].x, (ai)[0].y, (ai)[0].z, (ai)[0].w, \
                           (ai)[1].x, (ai)[1].y, (ai)[1].z, (ai)[1].w}; \
        const float xr[8] = {(xi0).x, (xi0).y, (xi0).z, (xi0).w, \
                             (xi1).x, (xi1).y, (xi1).z, (xi1).w}; \
        _Pragma("unroll") \
        for (int s = 0; s < 8; ++s) { \
            float e = mur + xr[s]; \
            e = fmaxf(e, 0.2f * e); \
            float w = (am[s] > 0) ? __expf(e) : 0.0f; \
            asm("cvt.rna.tf32.f32 %0, %1;" : "=r"(wt[s]) : "f"(w)); \
            dsum += __uint_as_float(wt[s]); \
        } \
        uint32_t* wp = (uint32_t*)(Ws + ((t) & 1) * WSTAGE_F + wrow * WSTR + j8); \
        *(uint4*)wp       = make_uint4(wt[0], wt[1], wt[2], wt[3]); \
        *(uint4*)(wp + 4) = make_uint4(wt[4], wt[5], wt[6], wt[7]); \
    } while (0)

    // Buffer convention: tile k lives in adjA/xiA when k is even, adjB/xiB when odd.
    int4 adjA[2], adjB[2];
    float4 xiA0, xiA1, xiB0, xiB1;

    // prologue
    CPB(0); asm volatile("cp.async.commit_group;" ::: "memory");
    CPB(1); asm volatile("cp.async.commit_group;" ::: "memory");
    LDPRE(0, adjA, xiA0, xiA1);
    GENW(0, adjA, xiA0, xiA1);
    LDPRE(1, adjB, xiB0, xiB1);     // tile 1 (odd) -> B buffers

    for (int t = 0; t < NT; ++t) {
        if (t < NT - 1) asm volatile("cp.async.wait_group 1;" ::: "memory");
        else            asm volatile("cp.async.wait_group 0;" ::: "memory");
        __syncthreads();   // B(t) + W(t) visible; all reads of stage (t+2)%3 done

        if (t + 2 < NT) { CPB(t + 2); asm volatile("cp.async.commit_group;" ::: "memory"); }

        // ---- MMA over W(t) x B(t) ----
        {
            const uint32_t* Wst = (const uint32_t*)(Ws + (t & 1) * WSTAGE_F);
            const uint32_t* Bst = (const uint32_t*)(Bss + (t % 3) * BSTAGE_F);
#pragma unroll
            for (int ks = 0; ks < 4; ++ks) {
                uint32_t a[2][4];
#pragma unroll
                for (int mt = 0; mt < 2; ++mt) {
                    const int rb = m0 + mt * 16;
                    a[mt][0] = Wst[(rb + g) * WSTR + ks * 8 + tq];
                    a[mt][1] = Wst[(rb + g + 8) * WSTR + ks * 8 + tq];
                    a[mt][2] = Wst[(rb + g) * WSTR + ks * 8 + tq + 4];
                    a[mt][3] = Wst[(rb + g + 8) * WSTR + ks * 8 + tq + 4];
                }
#pragma unroll
                for (int nt = 0; nt < 8; ++nt) {
                    const uint32_t b0 = Bst[(n0 + nt * 8 + g) * WSTR + ks * 8 + tq];
                    const uint32_t b1 = Bst[(n0 + nt * 8 + g) * WSTR + ks * 8 + tq + 4];
                    mma_tf32(acc[0][nt], a[0], b0, b1);
                    mma_tf32(acc[1][nt], a[1], b0, b1);
                }
            }
        }

        // ---- produce W(t+1) from tile-(t+1)-parity buffer; prefetch t+2 ----
        if (t + 1 < NT) {
            if ((t + 1) & 1) GENW(t + 1, adjB, xiB0, xiB1);   // t+1 odd  -> B
            else             GENW(t + 1, adjA, xiA0, xiA1);   // t+1 even -> A
            if (t + 2 < NT) {
                if ((t + 2) & 1) LDPRE(t + 2, adjB, xiB0, xiB1);   // t+2 odd  -> B
                else             LDPRE(t + 2, adjA, xiA0, xiA1);   // t+2 even -> A
            }
        }
    }

    // ---- denominators: reduce over the 4 j-chunk threads of each row ----
    {
        float s = dsum;
        s += __shfl_xor_sync(0xFFFFFFFFu, s, 1);
        s += __shfl_xor_sync(0xFFFFFFFFu, s, 2);
        if ((tid & 3) == 0) rs[wrow] = s;
    }
    __syncthreads();

    // ---- epilogue: divide + ELU + store ----
    float inv[4];
#pragma unroll
    for (int r = 0; r < 4; ++r) inv[r] = 1.0f / rs[m0 + r * 8 + g];
#pragma unroll
    for (int mt = 0; mt < 2; ++mt) {
#pragma unroll
        for (int nt = 0; nt < 8; ++nt) {
            const int col = n0 + nt * 8 + 2 * tq;
            const int ra = row0 + m0 + mt * 16 + g;
            float v0 = acc[mt][nt][0] * inv[mt * 2];
            float v1 = acc[mt][nt][1] * inv[mt * 2];
            float v2 = acc[mt][nt][2] * inv[mt * 2 + 1];
            float v3 = acc[mt][nt][3] * inv[mt * 2 + 1];
            float2 o0, o1;
            o0.x = (v0 > 0.f) ? v0 : expm1f(v0);
            o0.y = (v1 > 0.f) ? v1 : expm1f(v1);
            o1.x = (v2 > 0.f) ? v2 : expm1f(v2);
            o1.y = (v3 > 0.f) ? v3 : expm1f(v3);
            *(float2*)&out[(size_t)ra * D_OUT + col] = o0;
            *(float2*)&out[(size_t)(ra + 8) * D_OUT + col] = o1;
        }
    }
#undef CPB
#undef LDPRE
#undef GENW
}

// ============================================================================
extern "C" void kernel_launch(void* const* d_in, const int* in_sizes, int n_in,
                              void* d_out, int out_size) {
    const float* F   = (const float*)d_in[0];
    const int*   adj = (const int*)d_in[1];
    const float* Wp  = (const float*)d_in[2];
    const float* wmu = (const float*)d_in[3];
    const float* wxi = (const float*)d_in[4];
    float* out = (float*)d_out;

    cudaFuncSetAttribute(attn_kernel, cudaFuncAttributeMaxDynamicSharedMemorySize, ATTN_SMEM);

    dim3 g1(N_NODES / G1_TM, D_OUT / G1_TN);
    gemm1_kernel<<<g1, 256>>>(F, Wp);
    muxi_kernel<<<N_NODES / 8, 256>>>(wmu, wxi);
    dim3 gt(N_NODES / 32, D_OUT / 32);
    transpose_kernel<<<gt, 256>>>();
    attn_kernel<<<N_NODES / TM, 256, ATTN_SMEM>>>(adj, out);
}